// round 1
// baseline (speedup 1.0000x reference)
#include <cuda_runtime.h>
#include <cuda_bf16.h>

// Problem constants (shapes are fixed by the reference; T taken from in_sizes)
#define HDIM 16
#define UDIM 7
#define HID  64
#define XDIM 23   // HDIM + UDIM

__global__ __launch_bounds__(64, 1)
void node_scan_kernel(const float* __restrict__ U,
                      const float* __restrict__ W1, const float* __restrict__ b1,
                      const float* __restrict__ W2, const float* __restrict__ b2,
                      const float* __restrict__ W3, const float* __restrict__ b3,
                      const float* __restrict__ wd, const float* __restrict__ bd,
                      const float* __restrict__ wt, const float* __restrict__ bt,
                      const float* __restrict__ wc, const float* __restrict__ bc,
                      const float* __restrict__ h0,
                      float* __restrict__ out, int T)
{
    __shared__ __align__(16) float sx[24];    // x = [h(16), u(7)], sx[23]=0 pad
    __shared__ __align__(16) float sz1[64];
    __shared__ __align__(16) float sz2[64];
    __shared__ float sp[16];                  // W3 partials (cols 32..63)
    __shared__ float srw[3][16];              // wd, wt, wc
    __shared__ float srb[3];                  // bd, bt, bc
    __shared__ float sb3[16];

    const int tid = threadIdx.x;
    const float dt = (float)(5.0 / 60.0);

    // ---- load per-thread weights into registers ----
    float w1r[24];
    #pragma unroll
    for (int j = 0; j < XDIM; ++j) w1r[j] = W1[tid * XDIM + j];
    w1r[23] = 0.0f;
    const float b1r = b1[tid];

    float w2r[64];
    #pragma unroll
    for (int j = 0; j < HID; ++j) w2r[j] = W2[tid * HID + j];
    const float b2r = b2[tid];

    // W3 split: warp0 lanes 0-15 -> rows, cols 0..31 ; lanes 16-31 -> rows, cols 32..63
    const int r3 = tid & 15;
    const int cb = (tid & 16) * 2;   // 0 or 32
    float w3r[32];
    #pragma unroll
    for (int j = 0; j < 32; ++j) w3r[j] = W3[r3 * HID + cb + j];

    if (tid < 16) {
        sx[tid]     = h0[tid];
        sb3[tid]    = b3[tid];
        srw[0][tid] = wd[tid];
        srw[1][tid] = wt[tid];
        srw[2][tid] = wc[tid];
    }
    if (tid == 0) {
        srb[0] = bd[0]; srb[1] = bt[0]; srb[2] = bc[0];
        sx[23] = 0.0f;
    }

    // prefetch u_0
    float ureg = (tid < UDIM) ? U[tid] : 0.0f;

    const float4* sxv  = (const float4*)sx;
    const float4* sz1v = (const float4*)sz1;
    const float4* sz2v = (const float4*)sz2;

    for (int t = 0; t < T; ++t) {
        if (tid < UDIM) sx[HDIM + tid] = ureg;
        __syncthreads();                         // B1: x = [h_t, u_t] visible

        // prefetch u_{t+1} (latency hidden by the step body)
        if (tid < UDIM && (t + 1) < T) ureg = U[(t + 1) * UDIM + tid];

        // ---- layer 1: z1 = tanh(W1 x + b1), one row per thread ----
        {
            float a0 = b1r, a1 = 0.f, a2 = 0.f, a3 = 0.f;
            #pragma unroll
            for (int q = 0; q < 6; ++q) {
                float4 v = sxv[q];
                a0 = fmaf(w1r[4*q+0], v.x, a0);
                a1 = fmaf(w1r[4*q+1], v.y, a1);
                a2 = fmaf(w1r[4*q+2], v.z, a2);
                a3 = fmaf(w1r[4*q+3], v.w, a3);
            }
            sz1[tid] = tanhf((a0 + a1) + (a2 + a3));
        }
        __syncthreads();                         // B2: z1 ready

        // ---- layer 2: z2 = tanh(W2 z1 + b2), one row per thread ----
        {
            float a0 = b2r, a1 = 0.f, a2 = 0.f, a3 = 0.f;
            #pragma unroll
            for (int q = 0; q < 16; ++q) {
                float4 v = sz1v[q];
                a0 = fmaf(w2r[4*q+0], v.x, a0);
                a1 = fmaf(w2r[4*q+1], v.y, a1);
                a2 = fmaf(w2r[4*q+2], v.z, a2);
                a3 = fmaf(w2r[4*q+3], v.w, a3);
            }
            sz2[tid] = tanhf((a0 + a1) + (a2 + a3));
        }
        __syncthreads();                         // B3: z2 ready

        // ---- layer 3 (warp0, no intra-warp divergence) + readouts (warp1) ----
        float pr = 0.0f;
        if (tid < 32) {
            const int q0 = (tid & 16) >> 1;      // float4 offset: 0 or 8
            float c0 = 0.f, c1 = 0.f, c2 = 0.f, c3 = 0.f;
            #pragma unroll
            for (int q = 0; q < 8; ++q) {
                float4 v = sz2v[q0 + q];
                c0 = fmaf(w3r[4*q+0], v.x, c0);
                c1 = fmaf(w3r[4*q+1], v.y, c1);
                c2 = fmaf(w3r[4*q+2], v.z, c2);
                c3 = fmaf(w3r[4*q+3], v.w, c3);
            }
            pr = (c0 + c1) + (c2 + c3);
            if (tid >= 16) sp[tid & 15] = pr;    // cols 32..63 partial
        } else if (tid < 35) {
            // readouts use h_t (sx is not updated until after B4)
            const int k = tid - 32;
            float acc = srb[k];
            #pragma unroll
            for (int j = 0; j < HDIM; ++j)
                acc = fmaf(srw[k][j], sx[j], acc);
            out[(size_t)k * (size_t)T + (size_t)t] = acc;
        }
        __syncthreads();                         // B4: partials + readout reads done

        // ---- Euler update: h += dt * (W3 z2 + b3) ----
        if (tid < 16) {
            float dh = pr + sp[tid] + sb3[tid];
            sx[tid] = fmaf(dt, dh, sx[tid]);
        }
        // next iteration's B1 makes the new h visible to all threads
    }

    __syncthreads();
    if (tid < HDIM) out[(size_t)3 * (size_t)T + tid] = sx[tid];
}

extern "C" void kernel_launch(void* const* d_in, const int* in_sizes, int n_in,
                              void* d_out, int out_size)
{
    const float* U  = (const float*)d_in[0];
    const float* W1 = (const float*)d_in[1];
    const float* b1 = (const float*)d_in[2];
    const float* W2 = (const float*)d_in[3];
    const float* b2 = (const float*)d_in[4];
    const float* W3 = (const float*)d_in[5];
    const float* b3 = (const float*)d_in[6];
    const float* wd = (const float*)d_in[7];
    const float* bd = (const float*)d_in[8];
    const float* wt = (const float*)d_in[9];
    const float* bt = (const float*)d_in[10];
    const float* wc = (const float*)d_in[11];
    const float* bc = (const float*)d_in[12];
    const float* h0 = (const float*)d_in[13];
    float* out = (float*)d_out;

    const int T = in_sizes[0] / UDIM;

    node_scan_kernel<<<1, 64>>>(U, W1, b1, W2, b2, W3, b3,
                                wd, bd, wt, bt, wc, bc, h0, out, T);
}